// round 1
// baseline (speedup 1.0000x reference)
#include <cuda_runtime.h>
#include <math.h>

#define NNODE   512
#define NGRAPH  8
#define E_DIM   1024
#define NHEADS  16
#define HD      64
#define NB      (NGRAPH*NHEADS)     // 128 heads
#define NROWS   (NNODE*NGRAPH)      // 4096
#define SCALING 0.125f              // 64^-0.5

// Scratch (device globals: allocation-free rule)
__device__ float g_Q[NB*NNODE*HD];
__device__ float g_K[NB*NNODE*HD];
__device__ float g_V[NB*NNODE*HD];
__device__ float g_AO[NROWS*E_DIM];

__device__ __forceinline__ unsigned f2tf32(float x){
    unsigned r; asm("cvt.rna.tf32.f32 %0, %1;" : "=r"(r) : "f"(x)); return r;
}

__device__ __forceinline__ void mma_tf32(float c[4], const unsigned a[4], const unsigned b[2]){
    asm volatile(
        "mma.sync.aligned.m16n8k8.row.col.f32.tf32.tf32.f32 "
        "{%0,%1,%2,%3}, {%4,%5,%6,%7}, {%8,%9}, {%0,%1,%2,%3};"
        : "+f"(c[0]), "+f"(c[1]), "+f"(c[2]), "+f"(c[3])
        : "r"(a[0]), "r"(a[1]), "r"(a[2]), "r"(a[3]), "r"(b[0]), "r"(b[1]));
}

// ---------------------------------------------------------------------------
// GEMM 1: qkv = query @ in_w^T + in_b, scattered into per-head Q/K/V layouts.
// C[4096,3072] = X[4096,1024] * W[3072,1024]^T   (NT)
// BM=128 BN=128 BK=32, 256 thr, warp grid 2x4, warp tile 64x32.
// ---------------------------------------------------------------------------
#define G_BM 128
#define G_BN 128
#define G_BK 32
#define G_AS 44   // 44 % 32 == 12 -> conflict-free fragment LDS

__global__ __launch_bounds__(256)
void gemm_qkv_kernel(const float* __restrict__ X, const float* __restrict__ W,
                     const float* __restrict__ bias)
{
    __shared__ unsigned As[G_BM*G_AS];
    __shared__ unsigned Bs[G_BN*G_AS];

    const int tid  = threadIdx.x;
    const int wid  = tid >> 5, lane = tid & 31;
    const int wm   = wid >> 2, wn = wid & 3;
    const int g    = lane >> 2, tg = lane & 3;
    const int bm0  = blockIdx.y * G_BM;
    const int bn0  = blockIdx.x * G_BN;

    float acc[4][4][4];
    #pragma unroll
    for (int i=0;i<4;i++)
        #pragma unroll
        for (int j=0;j<4;j++)
            #pragma unroll
            for (int k=0;k<4;k++) acc[i][j][k]=0.f;

    const int lrow = tid >> 3;
    const int lk4  = (tid & 7) << 2;
    const float* Ap = X + (size_t)(bm0 + lrow) * E_DIM + lk4;
    const float* Bp = W + (size_t)(bn0 + lrow) * E_DIM + lk4;

    for (int kt = 0; kt < E_DIM; kt += G_BK) {
        __syncthreads();
        #pragma unroll
        for (int r = 0; r < G_BM; r += 32) {
            float4 av = *(const float4*)(Ap + (size_t)r*E_DIM + kt);
            float4 bv = *(const float4*)(Bp + (size_t)r*E_DIM + kt);
            uint4 at = make_uint4(f2tf32(av.x), f2tf32(av.y), f2tf32(av.z), f2tf32(av.w));
            uint4 bt = make_uint4(f2tf32(bv.x), f2tf32(bv.y), f2tf32(bv.z), f2tf32(bv.w));
            *(uint4*)&As[(lrow + r)*G_AS + lk4] = at;
            *(uint4*)&Bs[(lrow + r)*G_AS + lk4] = bt;
        }
        __syncthreads();

        #pragma unroll
        for (int ks = 0; ks < G_BK; ks += 8) {
            unsigned a[4][4], b[4][2];
            #pragma unroll
            for (int mt = 0; mt < 4; mt++) {
                int r0 = wm*64 + mt*16 + g;
                a[mt][0] = As[r0*G_AS + ks + tg];
                a[mt][1] = As[(r0+8)*G_AS + ks + tg];
                a[mt][2] = As[r0*G_AS + ks + tg + 4];
                a[mt][3] = As[(r0+8)*G_AS + ks + tg + 4];
            }
            #pragma unroll
            for (int nt = 0; nt < 4; nt++) {
                int c0 = wn*32 + nt*8 + g;
                b[nt][0] = Bs[c0*G_AS + ks + tg];
                b[nt][1] = Bs[c0*G_AS + ks + tg + 4];
            }
            #pragma unroll
            for (int mt = 0; mt < 4; mt++)
                #pragma unroll
                for (int nt = 0; nt < 4; nt++)
                    mma_tf32(acc[mt][nt], a[mt], b[nt]);
        }
    }

    // Epilogue: +bias, scatter to per-head Q(scaled)/K/V
    #pragma unroll
    for (int mt = 0; mt < 4; mt++)
        #pragma unroll
        for (int nt = 0; nt < 4; nt++)
            #pragma unroll
            for (int i = 0; i < 4; i++) {
                int r = bm0 + wm*64 + mt*16 + g + ((i>>1)<<3);
                int c = bn0 + wn*32 + nt*8 + 2*tg + (i&1);
                float v = acc[mt][nt][i] + bias[c];
                int which = c >> 10;
                int e = c & 1023, h = e >> 6, d = e & 63;
                int n = r >> 3, gg = r & 7;
                int idx = ((gg*NHEADS + h)*NNODE + n)*HD + d;
                if (which == 0)      g_Q[idx] = v * SCALING;
                else if (which == 1) g_K[idx] = v;
                else                 g_V[idx] = v;
            }
}

// ---------------------------------------------------------------------------
// Fused attention: S = Q K^T + bias; P = tanh(gaw) * softmax(S); O = P V
// One CTA per (head, 64-row block). 256 thr = 8 warps (2x4).
// ---------------------------------------------------------------------------
#define QK_ST 76    // 76 % 32 == 12 -> conflict-free both A and B frag patterns
#define S_ST  524   // 524 % 32 == 12

#define ATTN_SMEM ((64*QK_ST + 128*QK_ST + 64*S_ST) * 4)

__global__ __launch_bounds__(256)
void attn_kernel(const float* __restrict__ bias, const float* __restrict__ gaw)
{
    extern __shared__ unsigned sm[];
    unsigned* Qs  = sm;
    unsigned* KVs = sm + 64*QK_ST;
    float*    Ssf = (float*)(KVs + 128*QK_ST);
    unsigned* Ssu = (unsigned*)Ssf;

    const int b   = blockIdx.x;          // head
    const int rb  = blockIdx.y;          // 64-row block
    const int tid = threadIdx.x;
    const int wid = tid >> 5, lane = tid & 31;
    const int wm  = wid >> 2, wn = wid & 3;
    const int g   = lane >> 2, tg = lane & 3;

    // Load Q tile [64,64] -> tf32 smem
    {
        const float* Qg = g_Q + ((size_t)b*NNODE + rb*64)*HD;
        #pragma unroll
        for (int i = tid; i < 64*16; i += 256) {
            int r = i >> 4, c4 = (i & 15) << 2;
            float4 v = *(const float4*)(Qg + r*HD + c4);
            *(uint4*)&Qs[r*QK_ST + c4] =
                make_uint4(f2tf32(v.x), f2tf32(v.y), f2tf32(v.z), f2tf32(v.w));
        }
    }

    // ---- Phase 1: scores, 4 chunks of 128 cols ----
    for (int ch = 0; ch < 4; ch++) {
        __syncthreads();
        const float* Kg = g_K + ((size_t)b*NNODE + ch*128)*HD;
        #pragma unroll
        for (int i = tid; i < 128*16; i += 256) {
            int r = i >> 4, c4 = (i & 15) << 2;
            float4 v = *(const float4*)(Kg + r*HD + c4);
            *(uint4*)&KVs[r*QK_ST + c4] =
                make_uint4(f2tf32(v.x), f2tf32(v.y), f2tf32(v.z), f2tf32(v.w));
        }
        __syncthreads();

        float s[2][4][4];
        #pragma unroll
        for (int i=0;i<2;i++)
            #pragma unroll
            for (int j=0;j<4;j++)
                #pragma unroll
                for (int k=0;k<4;k++) s[i][j][k]=0.f;

        #pragma unroll
        for (int ks = 0; ks < HD; ks += 8) {
            unsigned a[2][4], bb[4][2];
            #pragma unroll
            for (int mt = 0; mt < 2; mt++) {
                int r0 = wm*32 + mt*16 + g;
                a[mt][0] = Qs[r0*QK_ST + ks + tg];
                a[mt][1] = Qs[(r0+8)*QK_ST + ks + tg];
                a[mt][2] = Qs[r0*QK_ST + ks + tg + 4];
                a[mt][3] = Qs[(r0+8)*QK_ST + ks + tg + 4];
            }
            #pragma unroll
            for (int nt = 0; nt < 4; nt++) {
                int c0 = wn*32 + nt*8 + g;
                bb[nt][0] = KVs[c0*QK_ST + ks + tg];
                bb[nt][1] = KVs[c0*QK_ST + ks + tg + 4];
            }
            #pragma unroll
            for (int mt = 0; mt < 2; mt++)
                #pragma unroll
                for (int nt = 0; nt < 4; nt++)
                    mma_tf32(s[mt][nt], a[mt], bb[nt]);
        }

        // +attn_bias, store scores to smem
        const float* bp = bias + ((size_t)b*NNODE + rb*64)*NNODE + ch*128;
        #pragma unroll
        for (int mt = 0; mt < 2; mt++)
            #pragma unroll
            for (int nt = 0; nt < 4; nt++)
                #pragma unroll
                for (int ii = 0; ii < 2; ii++) {
                    int lr = wm*32 + mt*16 + g + ii*8;
                    int lc = wn*32 + nt*8 + 2*tg;
                    float2 bv = *(const float2*)(bp + (size_t)lr*NNODE + lc);
                    float2 sv = make_float2(s[mt][nt][ii*2] + bv.x,
                                            s[mt][nt][ii*2+1] + bv.y);
                    *(float2*)&Ssf[lr*S_ST + ch*128 + lc] = sv;
                }
    }
    __syncthreads();

    // ---- Phase 2: softmax rows, multiply tanh(gaw), write tf32 probs ----
    {
        #pragma unroll 1
        for (int rr = 0; rr < 8; rr++) {
            int lr = wid*8 + rr;
            float v[16];
            float mx = -1e30f;
            #pragma unroll
            for (int j = 0; j < 16; j++) {
                v[j] = Ssf[lr*S_ST + lane + 32*j];
                mx = fmaxf(mx, v[j]);
            }
            #pragma unroll
            for (int off = 16; off > 0; off >>= 1)
                mx = fmaxf(mx, __shfl_xor_sync(0xffffffffu, mx, off));
            float sum = 0.f;
            #pragma unroll
            for (int j = 0; j < 16; j++) { v[j] = __expf(v[j] - mx); sum += v[j]; }
            #pragma unroll
            for (int off = 16; off > 0; off >>= 1)
                sum += __shfl_xor_sync(0xffffffffu, sum, off);
            float inv = 1.f / sum;

            const float* gp = gaw + ((size_t)b*NNODE + rb*64 + lr)*NNODE;
            #pragma unroll
            for (int j = 0; j < 16; j++) {
                float t = tanhf(gp[lane + 32*j]);
                Ssu[lr*S_ST + lane + 32*j] = f2tf32(t * v[j] * inv);
            }
        }
    }

    // ---- Phase 3: O = P V  (64x64 output, 4 V-chunks of 128) ----
    float o[2][2][4];
    #pragma unroll
    for (int i=0;i<2;i++)
        #pragma unroll
        for (int j=0;j<2;j++)
            #pragma unroll
            for (int k=0;k<4;k++) o[i][j][k]=0.f;

    for (int ch = 0; ch < 4; ch++) {
        __syncthreads();
        const float* Vg = g_V + ((size_t)b*NNODE + ch*128)*HD;
        #pragma unroll
        for (int i = tid; i < 128*16; i += 256) {
            int r = i >> 4, c4 = (i & 15) << 2;
            float4 v = *(const float4*)(Vg + r*HD + c4);
            *(uint4*)&KVs[r*QK_ST + c4] =
                make_uint4(f2tf32(v.x), f2tf32(v.y), f2tf32(v.z), f2tf32(v.w));
        }
        __syncthreads();

        #pragma unroll
        for (int ks = 0; ks < 128; ks += 8) {
            unsigned a[2][4], bb[2][2];
            #pragma unroll
            for (int mt = 0; mt < 2; mt++) {
                int r0 = wm*32 + mt*16 + g;
                int kc = ch*128 + ks;
                a[mt][0] = Ssu[r0*S_ST + kc + tg];
                a[mt][1] = Ssu[(r0+8)*S_ST + kc + tg];
                a[mt][2] = Ssu[r0*S_ST + kc + tg + 4];
                a[mt][3] = Ssu[(r0+8)*S_ST + kc + tg + 4];
            }
            #pragma unroll
            for (int nt = 0; nt < 2; nt++) {
                int c0 = wn*16 + nt*8 + g;
                bb[nt][0] = KVs[(ks + tg)*QK_ST + c0];
                bb[nt][1] = KVs[(ks + tg + 4)*QK_ST + c0];
            }
            #pragma unroll
            for (int mt = 0; mt < 2; mt++)
                #pragma unroll
                for (int nt = 0; nt < 2; nt++)
                    mma_tf32(o[mt][nt], a[mt], bb[nt]);
        }
    }

    // Epilogue -> g_AO[(n*8+g)*1024 + h*64 + d]
    const int gg = b >> 4, h = b & 15;
    #pragma unroll
    for (int mt = 0; mt < 2; mt++)
        #pragma unroll
        for (int nt = 0; nt < 2; nt++)
            #pragma unroll
            for (int ii = 0; ii < 2; ii++) {
                int n = rb*64 + wm*32 + mt*16 + g + ii*8;
                int d = wn*16 + nt*8 + 2*tg;
                float2 val = make_float2(o[mt][nt][ii*2], o[mt][nt][ii*2+1]);
                *(float2*)&g_AO[(size_t)(n*NGRAPH + gg)*E_DIM + h*HD + d] = val;
            }
}

// ---------------------------------------------------------------------------
// GEMM 3: out = attnO @ out_w^T + out_b.  C[4096,1024] = A[4096,1024]*W[1024,1024]^T
// ---------------------------------------------------------------------------
__global__ __launch_bounds__(256)
void gemm_out_kernel(const float* __restrict__ W, const float* __restrict__ bias,
                     float* __restrict__ out)
{
    __shared__ unsigned As[G_BM*G_AS];
    __shared__ unsigned Bs[G_BN*G_AS];

    const int tid  = threadIdx.x;
    const int wid  = tid >> 5, lane = tid & 31;
    const int wm   = wid >> 2, wn = wid & 3;
    const int g    = lane >> 2, tg = lane & 3;
    const int bm0  = blockIdx.y * G_BM;
    const int bn0  = blockIdx.x * G_BN;

    float acc[4][4][4];
    #pragma unroll
    for (int i=0;i<4;i++)
        #pragma unroll
        for (int j=0;j<4;j++)
            #pragma unroll
            for (int k=0;k<4;k++) acc[i][j][k]=0.f;

    const int lrow = tid >> 3;
    const int lk4  = (tid & 7) << 2;
    const float* Ap = g_AO + (size_t)(bm0 + lrow) * E_DIM + lk4;
    const float* Bp = W    + (size_t)(bn0 + lrow) * E_DIM + lk4;

    for (int kt = 0; kt < E_DIM; kt += G_BK) {
        __syncthreads();
        #pragma unroll
        for (int r = 0; r < G_BM; r += 32) {
            float4 av = *(const float4*)(Ap + (size_t)r*E_DIM + kt);
            float4 bv = *(const float4*)(Bp + (size_t)r*E_DIM + kt);
            uint4 at = make_uint4(f2tf32(av.x), f2tf32(av.y), f2tf32(av.z), f2tf32(av.w));
            uint4 bt = make_uint4(f2tf32(bv.x), f2tf32(bv.y), f2tf32(bv.z), f2tf32(bv.w));
            *(uint4*)&As[(lrow + r)*G_AS + lk4] = at;
            *(uint4*)&Bs[(lrow + r)*G_AS + lk4] = bt;
        }
        __syncthreads();

        #pragma unroll
        for (int ks = 0; ks < G_BK; ks += 8) {
            unsigned a[4][4], b[4][2];
            #pragma unroll
            for (int mt = 0; mt < 4; mt++) {
                int r0 = wm*64 + mt*16 + g;
                a[mt][0] = As[r0*G_AS + ks + tg];
                a[mt][1] = As[(r0+8)*G_AS + ks + tg];
                a[mt][2] = As[r0*G_AS + ks + tg + 4];
                a[mt][3] = As[(r0+8)*G_AS + ks + tg + 4];
            }
            #pragma unroll
            for (int nt = 0; nt < 4; nt++) {
                int c0 = wn*32 + nt*8 + g;
                b[nt][0] = Bs[c0*G_AS + ks + tg];
                b[nt][1] = Bs[c0*G_AS + ks + tg + 4];
            }
            #pragma unroll
            for (int mt = 0; mt < 4; mt++)
                #pragma unroll
                for (int nt = 0; nt < 4; nt++)
                    mma_tf32(acc[mt][nt], a[mt], b[nt]);
        }
    }

    #pragma unroll
    for (int mt = 0; mt < 4; mt++)
        #pragma unroll
        for (int nt = 0; nt < 4; nt++)
            #pragma unroll
            for (int ii = 0; ii < 2; ii++) {
                int r = bm0 + wm*64 + mt*16 + g + ii*8;
                int c = bn0 + wn*32 + nt*8 + 2*tg;
                float2 bv = *(const float2*)(bias + c);
                float2 val = make_float2(acc[mt][nt][ii*2] + bv.x,
                                         acc[mt][nt][ii*2+1] + bv.y);
                *(float2*)&out[(size_t)r*E_DIM + c] = val;
            }
}

// ---------------------------------------------------------------------------
extern "C" void kernel_launch(void* const* d_in, const int* in_sizes, int n_in,
                              void* d_out, int out_size)
{
    const float* query    = (const float*)d_in[0];
    const float* attnbias = (const float*)d_in[1];
    const float* gaw      = (const float*)d_in[2];
    const float* in_w     = (const float*)d_in[3];
    const float* in_b     = (const float*)d_in[4];
    const float* out_w    = (const float*)d_in[5];
    const float* out_b    = (const float*)d_in[6];
    float* out = (float*)d_out;

    cudaFuncSetAttribute(attn_kernel,
                         cudaFuncAttributeMaxDynamicSharedMemorySize, ATTN_SMEM);

    dim3 g1(3*E_DIM/G_BN, NROWS/G_BM);   // (24, 32)
    gemm_qkv_kernel<<<g1, 256>>>(query, in_w, in_b);

    dim3 g2(NB, NNODE/64);               // (128, 8)
    attn_kernel<<<g2, 256, ATTN_SMEM>>>(attnbias, gaw);

    dim3 g3(E_DIM/G_BN, NROWS/G_BM);     // (8, 32)
    gemm_out_kernel<<<g3, 256>>>(out_w, out_b, out);
}

// round 2
// speedup vs baseline: 1.1731x; 1.1731x over previous
#include <cuda_runtime.h>
#include <math.h>

#define NNODE   512
#define NGRAPH  8
#define E_DIM   1024
#define NHEADS  16
#define HD      64
#define NB      (NGRAPH*NHEADS)     // 128 heads
#define NROWS   (NNODE*NGRAPH)      // 4096
#define SCALING 0.125f              // 64^-0.5

// Scratch (device globals: allocation-free rule)
// g_Q/g_K/g_V hold tf32-bit-pattern floats (pre-converted in GEMM1 epilogue).
__device__ float g_Q[NB*NNODE*HD];
__device__ float g_K[NB*NNODE*HD];
__device__ float g_V[NB*NNODE*HD];
__device__ float g_AO[NROWS*E_DIM];

__device__ __forceinline__ unsigned f2tf32(float x){
    unsigned r; asm("cvt.rna.tf32.f32 %0, %1;" : "=r"(r) : "f"(x)); return r;
}

__device__ __forceinline__ void mma_tf32(float c[4], const unsigned a[4], const unsigned b[2]){
    asm volatile(
        "mma.sync.aligned.m16n8k8.row.col.f32.tf32.tf32.f32 "
        "{%0,%1,%2,%3}, {%4,%5,%6,%7}, {%8,%9}, {%0,%1,%2,%3};"
        : "+f"(c[0]), "+f"(c[1]), "+f"(c[2]), "+f"(c[3])
        : "r"(a[0]), "r"(a[1]), "r"(a[2]), "r"(a[3]), "r"(b[0]), "r"(b[1]));
}

__device__ __forceinline__ unsigned smem_u32(const void* p){
    return (unsigned)__cvta_generic_to_shared(p);
}
__device__ __forceinline__ void cp16(unsigned dst, const void* src){
    asm volatile("cp.async.cg.shared.global [%0], [%1], 16;\n" :: "r"(dst), "l"(src));
}
__device__ __forceinline__ void cp_commit(){ asm volatile("cp.async.commit_group;\n" ::: "memory"); }
template<int N> __device__ __forceinline__ void cp_wait(){
    asm volatile("cp.async.wait_group %0;\n" :: "n"(N) : "memory");
}

__device__ __forceinline__ float fast_tanh(float x){
    float e = __expf(2.f*x);
    return 1.f - __fdividef(2.f, e + 1.f);
}

// ---------------------------------------------------------------------------
// Pipelined tf32 GEMM, C[rows,cols] = A[rows,1024] * W[cols,1024]^T (+bias)
// BM=128 BN=128 BK=32, 256 thr, warp grid 2x4, warp tile 64x32.
// 2-stage cp.async pipeline; raw fp32 in smem; cvt->tf32 in fragment loads.
// QKV=true: A=query, epilogue scatters tf32 Q(scaled)/K/V per-head.
// QKV=false: A=g_AO, epilogue writes fp32 out.
// ---------------------------------------------------------------------------
#define G_BM 128
#define G_BN 128
#define G_BK 32
#define G_ST 36    // 36 % 32 == 4 -> conflict-free fragment LDS; 36*4 % 16 == 0
#define G_AB (G_BM*G_ST)
#define GEMM_SMEM (4*G_AB*4)   // 2 stages x (A+B) = 73728 B

__device__ __forceinline__ void gemm_load_tile(const float* Ap, const float* Bp,
                                               float* as, float* bs,
                                               int lrow, int lk4)
{
    #pragma unroll
    for (int r = 0; r < G_BM; r += 32) {
        cp16(smem_u32(as + (lrow+r)*G_ST + lk4), Ap + (size_t)r*E_DIM);
        cp16(smem_u32(bs + (lrow+r)*G_ST + lk4), Bp + (size_t)r*E_DIM);
    }
}

template<bool QKV>
__global__ __launch_bounds__(256, 2)
void gemm_kernel(const float* __restrict__ Ain, const float* __restrict__ W,
                 const float* __restrict__ bias, float* __restrict__ Cout)
{
    extern __shared__ float sm[];
    const float* A = QKV ? Ain : (const float*)g_AO;

    const int tid  = threadIdx.x;
    const int wid  = tid >> 5, lane = tid & 31;
    const int wm   = wid >> 2, wn = wid & 3;
    const int g    = lane >> 2, tg = lane & 3;
    const int bm0  = blockIdx.y * G_BM;
    const int bn0  = blockIdx.x * G_BN;

    float acc[4][4][4];
    #pragma unroll
    for (int i=0;i<4;i++)
        #pragma unroll
        for (int j=0;j<4;j++)
            #pragma unroll
            for (int k=0;k<4;k++) acc[i][j][k]=0.f;

    const int lrow = tid >> 3;
    const int lk4  = (tid & 7) << 2;
    const float* Ap = A + (size_t)(bm0 + lrow) * E_DIM + lk4;
    const float* Bp = W + (size_t)(bn0 + lrow) * E_DIM + lk4;

    const int T = E_DIM / G_BK;  // 32 tiles
    gemm_load_tile(Ap, Bp, sm, sm + 2*G_AB, lrow, lk4);
    cp_commit();

    for (int t = 0; t < T; t++) {
        if (t + 1 < T) {
            int s = (t+1) & 1;
            gemm_load_tile(Ap + (t+1)*G_BK, Bp + (t+1)*G_BK,
                           sm + s*G_AB, sm + 2*G_AB + s*G_AB, lrow, lk4);
            cp_commit();
            cp_wait<1>();
        } else {
            cp_wait<0>();
        }
        __syncthreads();

        const float* as = sm + (t & 1)*G_AB;
        const float* bs = sm + 2*G_AB + (t & 1)*G_AB;

        #pragma unroll
        for (int ks = 0; ks < G_BK; ks += 8) {
            unsigned a[4][4], b[4][2];
            #pragma unroll
            for (int mt = 0; mt < 4; mt++) {
                int r0 = wm*64 + mt*16 + g;
                a[mt][0] = f2tf32(as[r0*G_ST + ks + tg]);
                a[mt][1] = f2tf32(as[(r0+8)*G_ST + ks + tg]);
                a[mt][2] = f2tf32(as[r0*G_ST + ks + tg + 4]);
                a[mt][3] = f2tf32(as[(r0+8)*G_ST + ks + tg + 4]);
            }
            #pragma unroll
            for (int nt = 0; nt < 4; nt++) {
                int c0 = wn*32 + nt*8 + g;
                b[nt][0] = f2tf32(bs[c0*G_ST + ks + tg]);
                b[nt][1] = f2tf32(bs[c0*G_ST + ks + tg + 4]);
            }
            #pragma unroll
            for (int mt = 0; mt < 4; mt++)
                #pragma unroll
                for (int nt = 0; nt < 4; nt++)
                    mma_tf32(acc[mt][nt], a[mt], b[nt]);
        }
        __syncthreads();
    }

    if (QKV) {
        // +bias, convert to tf32, scatter to per-head Q(scaled)/K/V
        #pragma unroll
        for (int mt = 0; mt < 4; mt++)
            #pragma unroll
            for (int nt = 0; nt < 4; nt++)
                #pragma unroll
                for (int i = 0; i < 4; i++) {
                    int r = bm0 + wm*64 + mt*16 + g + ((i>>1)<<3);
                    int c = bn0 + wn*32 + nt*8 + 2*tg + (i&1);
                    float v = acc[mt][nt][i] + bias[c];
                    int which = c >> 10;
                    int e = c & 1023, h = e >> 6, d = e & 63;
                    int n = r >> 3, gg = r & 7;
                    int idx = ((gg*NHEADS + h)*NNODE + n)*HD + d;
                    if (which == 0)      g_Q[idx] = __uint_as_float(f2tf32(v * SCALING));
                    else if (which == 1) g_K[idx] = __uint_as_float(f2tf32(v));
                    else                 g_V[idx] = __uint_as_float(f2tf32(v));
                }
    } else {
        #pragma unroll
        for (int mt = 0; mt < 4; mt++)
            #pragma unroll
            for (int nt = 0; nt < 4; nt++)
                #pragma unroll
                for (int ii = 0; ii < 2; ii++) {
                    int r = bm0 + wm*64 + mt*16 + g + ii*8;
                    int c = bn0 + wn*32 + nt*8 + 2*tg;
                    float2 bv = *(const float2*)(bias + c);
                    float2 val = make_float2(acc[mt][nt][ii*2] + bv.x,
                                             acc[mt][nt][ii*2+1] + bv.y);
                    *(float2*)&Cout[(size_t)r*E_DIM + c] = val;
                }
    }
}

// ---------------------------------------------------------------------------
// Flash-style fused attention: online softmax over 8 chunks of 64 KV cols.
// One CTA per (head, 64-row block). 256 thr = 8 warps (wm 2 x wn 4).
// P = tanh(gaw) * softmax(QK^T + bias); O = P V (online rescaled).
// smem ~77KB -> 2 CTAs/SM.
// ---------------------------------------------------------------------------
#define QK_ST 76    // 76 % 32 == 12 -> conflict-free; 76*4 % 16 == 0
#define P_ST  68    // 68 % 32 == 4  -> conflict-free A-frag loads
#define ATTN_F (3*64*QK_ST + 64*P_ST + 64 + 64 + 64*4)
#define ATTN_SMEM (ATTN_F*4)

__device__ __forceinline__ void attn_load64(float* dst, const float* src, int tid)
{
    #pragma unroll
    for (int j = 0; j < 4; j++) {
        int i = tid + 256*j, r = i >> 4, c4 = (i & 15) << 2;
        cp16(smem_u32(dst + r*QK_ST + c4), src + (size_t)r*HD + c4);
    }
}

__global__ __launch_bounds__(256, 2)
void attn_kernel(const float* __restrict__ bias, const float* __restrict__ gaw)
{
    extern __shared__ float sm[];
    float*    Qs   = sm;
    float*    Ks   = Qs + 64*QK_ST;
    float*    Vs   = Ks + 64*QK_ST;
    unsigned* Ps   = (unsigned*)(Vs + 64*QK_ST);
    float*    Mrow = (float*)(Ps + 64*P_ST);
    float*    Lrow = Mrow + 64;
    float*    Red  = Lrow + 64;      // [64][4]

    const int b   = blockIdx.x;          // head = gg*16 + h
    const int rb  = blockIdx.y;          // 64-row block
    const int tid = threadIdx.x;
    const int wid = tid >> 5, lane = tid & 31;
    const int wm  = wid >> 2, wn = wid & 3;
    const int g   = lane >> 2, tg = lane & 3;

    const float* Kg = g_K + (size_t)b*NNODE*HD;
    const float* Vg = g_V + (size_t)b*NNODE*HD;

    // Q tile + K chunk 0 (one cp.async group)
    {
        const float* Qg = g_Q + ((size_t)b*NNODE + rb*64)*HD;
        attn_load64(Qs, Qg, tid);
        attn_load64(Ks, Kg, tid);
        cp_commit();
    }
    if (tid < 64) { Mrow[tid] = -1e30f; Lrow[tid] = 0.f; }

    float o[2][2][4];
    #pragma unroll
    for (int i=0;i<2;i++)
        #pragma unroll
        for (int j=0;j<2;j++)
            #pragma unroll
            for (int k=0;k<4;k++) o[i][j][k]=0.f;

    const float* bp0 = bias + ((size_t)b*NNODE + rb*64)*NNODE;
    const float* gp0 = gaw  + ((size_t)b*NNODE + rb*64)*NNODE;

    for (int c = 0; c < 8; c++) {
        // prefetch bias / gaw for this chunk into registers
        float2 breg[8], greg[8];
        #pragma unroll
        for (int mt = 0; mt < 2; mt++)
            #pragma unroll
            for (int ii = 0; ii < 2; ii++)
                #pragma unroll
                for (int nt = 0; nt < 2; nt++) {
                    int lr = wm*32 + mt*16 + ii*8 + g;
                    int lc = c*64 + wn*16 + nt*8 + 2*tg;
                    int idx = (mt*2 + ii)*2 + nt;
                    breg[idx] = *(const float2*)(bp0 + (size_t)lr*NNODE + lc);
                    greg[idx] = *(const float2*)(gp0 + (size_t)lr*NNODE + lc);
                }

        __syncthreads();                 // all warps done with Vs (prev PV)
        attn_load64(Vs, Vg + (size_t)c*64*HD, tid);
        cp_commit();
        cp_wait<1>();                    // K_c (and Qs) ready
        __syncthreads();

        // ---- QK mma: s[2 rows][2 cols][4] over 64-wide chunk ----
        float s[2][2][4];
        #pragma unroll
        for (int i=0;i<2;i++)
            #pragma unroll
            for (int j=0;j<2;j++)
                #pragma unroll
                for (int k=0;k<4;k++) s[i][j][k]=0.f;

        #pragma unroll
        for (int ks = 0; ks < HD; ks += 8) {
            unsigned a[2][4], bb[2][2];
            #pragma unroll
            for (int mt = 0; mt < 2; mt++) {
                int r0 = wm*32 + mt*16 + g;
                a[mt][0] = __float_as_uint(Qs[r0*QK_ST + ks + tg]);
                a[mt][1] = __float_as_uint(Qs[(r0+8)*QK_ST + ks + tg]);
                a[mt][2] = __float_as_uint(Qs[r0*QK_ST + ks + tg + 4]);
                a[mt][3] = __float_as_uint(Qs[(r0+8)*QK_ST + ks + tg + 4]);
            }
            #pragma unroll
            for (int nt = 0; nt < 2; nt++) {
                int c0 = wn*16 + nt*8 + g;
                bb[nt][0] = __float_as_uint(Ks[c0*QK_ST + ks + tg]);
                bb[nt][1] = __float_as_uint(Ks[c0*QK_ST + ks + tg + 4]);
            }
            #pragma unroll
            for (int mt = 0; mt < 2; mt++)
                #pragma unroll
                for (int nt = 0; nt < 2; nt++)
                    mma_tf32(s[mt][nt], a[mt], bb[nt]);
        }

        // + bias
        #pragma unroll
        for (int mt = 0; mt < 2; mt++)
            #pragma unroll
            for (int ii = 0; ii < 2; ii++)
                #pragma unroll
                for (int nt = 0; nt < 2; nt++) {
                    int idx = (mt*2 + ii)*2 + nt;
                    s[mt][nt][ii*2]   += breg[idx].x;
                    s[mt][nt][ii*2+1] += breg[idx].y;
                }

        // ---- chunk row max (intra-thread -> quad shfl -> cross-warp) ----
        #pragma unroll
        for (int mt = 0; mt < 2; mt++)
            #pragma unroll
            for (int ii = 0; ii < 2; ii++) {
                float v = fmaxf(fmaxf(s[mt][0][ii*2], s[mt][0][ii*2+1]),
                                fmaxf(s[mt][1][ii*2], s[mt][1][ii*2+1]));
                v = fmaxf(v, __shfl_xor_sync(0xffffffffu, v, 1));
                v = fmaxf(v, __shfl_xor_sync(0xffffffffu, v, 2));
                if (tg == 0) Red[(wm*32 + mt*16 + ii*8 + g)*4 + wn] = v;
            }
        __syncthreads();

        float mnew[2][2], alpha[2][2], lold[2][2];
        #pragma unroll
        for (int mt = 0; mt < 2; mt++)
            #pragma unroll
            for (int ii = 0; ii < 2; ii++) {
                int row = wm*32 + mt*16 + ii*8 + g;
                float mc = fmaxf(fmaxf(Red[row*4], Red[row*4+1]),
                                 fmaxf(Red[row*4+2], Red[row*4+3]));
                float mo = Mrow[row];
                lold[mt][ii] = Lrow[row];
                float mn = fmaxf(mo, mc);
                mnew[mt][ii]  = mn;
                alpha[mt][ii] = __expf(mo - mn);
            }

        // ---- p = exp(s - mnew), row sums ----
        float psum[2][2];
        #pragma unroll
        for (int mt = 0; mt < 2; mt++)
            #pragma unroll
            for (int ii = 0; ii < 2; ii++) {
                float p0 = __expf(s[mt][0][ii*2]   - mnew[mt][ii]);
                float p1 = __expf(s[mt][0][ii*2+1] - mnew[mt][ii]);
                float p2 = __expf(s[mt][1][ii*2]   - mnew[mt][ii]);
                float p3 = __expf(s[mt][1][ii*2+1] - mnew[mt][ii]);
                s[mt][0][ii*2] = p0; s[mt][0][ii*2+1] = p1;
                s[mt][1][ii*2] = p2; s[mt][1][ii*2+1] = p3;
                float v = (p0 + p1) + (p2 + p3);
                v += __shfl_xor_sync(0xffffffffu, v, 1);
                v += __shfl_xor_sync(0xffffffffu, v, 2);
                psum[mt][ii] = v;
            }
        __syncthreads();   // Red reuse guard
        #pragma unroll
        for (int mt = 0; mt < 2; mt++)
            #pragma unroll
            for (int ii = 0; ii < 2; ii++)
                if (tg == 0) Red[(wm*32 + mt*16 + ii*8 + g)*4 + wn] = psum[mt][ii];
        __syncthreads();
        if (wn == 0 && tg == 0) {
            #pragma unroll
            for (int mt = 0; mt < 2; mt++)
                #pragma unroll
                for (int ii = 0; ii < 2; ii++) {
                    int row = wm*32 + mt*16 + ii*8 + g;
                    float sc = (Red[row*4] + Red[row*4+1]) + (Red[row*4+2] + Red[row*4+3]);
                    Lrow[row] = alpha[mt][ii]*lold[mt][ii] + sc;
                    Mrow[row] = mnew[mt][ii];
                }
        }

        // ---- p *= tanh(gaw); store tf32 P; rescale o ----
        #pragma unroll
        for (int mt = 0; mt < 2; mt++)
            #pragma unroll
            for (int ii = 0; ii < 2; ii++)
                #pragma unroll
                for (int nt = 0; nt < 2; nt++) {
                    int idx = (mt*2 + ii)*2 + nt;
                    int lr = wm*32 + mt*16 + ii*8 + g;
                    int lc = wn*16 + nt*8 + 2*tg;
                    unsigned u0 = f2tf32(s[mt][nt][ii*2]   * fast_tanh(greg[idx].x));
                    unsigned u1 = f2tf32(s[mt][nt][ii*2+1] * fast_tanh(greg[idx].y));
                    *(uint2*)&Ps[lr*P_ST + lc] = make_uint2(u0, u1);
                }
        #pragma unroll
        for (int mt = 0; mt < 2; mt++)
            #pragma unroll
            for (int nt = 0; nt < 2; nt++)
                #pragma unroll
                for (int k = 0; k < 4; k++)
                    o[mt][nt][k] *= alpha[mt][k>>1];

        // prefetch K_{c+1} (Ks free after QK mma; all warps past it)
        if (c < 7) attn_load64(Ks, Kg + (size_t)(c+1)*64*HD, tid);
        cp_commit();
        cp_wait<1>();                    // V_c ready
        __syncthreads();                 // Ps visible to all

        // ---- PV mma: o += P[64x64] * V[64x64] ----
        #pragma unroll
        for (int ks = 0; ks < 64; ks += 8) {
            unsigned a[2][4], bb[2][2];
            #pragma unroll
            for (int mt = 0; mt < 2; mt++) {
                int r0 = wm*32 + mt*16 + g;
                a[mt][0] = Ps[r0*P_ST + ks + tg];
                a[mt][1] = Ps[(r0+8)*P_ST + ks + tg];
                a[mt][2] = Ps[r0*P_ST + ks + tg + 4];
                a[mt][3] = Ps[(r0+8)*P_ST + ks + tg + 4];
            }
            #pragma unroll
            for (int nt = 0; nt < 2; nt++) {
                int c0 = wn*16 + nt*8 + g;
                bb[nt][0] = __float_as_uint(Vs[(ks + tg)*QK_ST + c0]);
                bb[nt][1] = __float_as_uint(Vs[(ks + tg + 4)*QK_ST + c0]);
            }
            #pragma unroll
            for (int mt = 0; mt < 2; mt++)
                #pragma unroll
                for (int nt = 0; nt < 2; nt++)
                    mma_tf32(o[mt][nt], a[mt], bb[nt]);
        }
    }

    __syncthreads();
    // normalize by running sum, write to g_AO[(n*8+gg)*1024 + h*64 + d]
    const int gg = b >> 4, h = b & 15;
    #pragma unroll
    for (int mt = 0; mt < 2; mt++)
        #pragma unroll
        for (int ii = 0; ii < 2; ii++) {
            int row = wm*32 + mt*16 + ii*8 + g;
            float inv = __fdividef(1.f, Lrow[row]);
            int n = rb*64 + row;
            #pragma unroll
            for (int nt = 0; nt < 2; nt++) {
                int d = wn*16 + nt*8 + 2*tg;
                float2 val = make_float2(o[mt][nt][ii*2]   * inv,
                                         o[mt][nt][ii*2+1] * inv);
                *(float2*)&g_AO[(size_t)(n*NGRAPH + gg)*E_DIM + h*HD + d] = val;
            }
        }
}

// ---------------------------------------------------------------------------
extern "C" void kernel_launch(void* const* d_in, const int* in_sizes, int n_in,
                              void* d_out, int out_size)
{
    const float* query    = (const float*)d_in[0];
    const float* attnbias = (const float*)d_in[1];
    const float* gaw      = (const float*)d_in[2];
    const float* in_w     = (const float*)d_in[3];
    const float* in_b     = (const float*)d_in[4];
    const float* out_w    = (const float*)d_in[5];
    const float* out_b    = (const float*)d_in[6];
    float* out = (float*)d_out;

    static int configured = 0;
    if (!configured) {
        cudaFuncSetAttribute(gemm_kernel<true>,
                             cudaFuncAttributeMaxDynamicSharedMemorySize, GEMM_SMEM);
        cudaFuncSetAttribute(gemm_kernel<false>,
                             cudaFuncAttributeMaxDynamicSharedMemorySize, GEMM_SMEM);
        cudaFuncSetAttribute(attn_kernel,
                             cudaFuncAttributeMaxDynamicSharedMemorySize, ATTN_SMEM);
        configured = 1;
    }

    dim3 g1(3*E_DIM/G_BN, NROWS/G_BM);   // (24, 32)
    gemm_kernel<true><<<g1, 256, GEMM_SMEM>>>(query, in_w, in_b, nullptr);

    dim3 g2(NB, NNODE/64);               // (128, 8)
    attn_kernel<<<g2, 256, ATTN_SMEM>>>(attnbias, gaw);

    dim3 g3(E_DIM/G_BN, NROWS/G_BM);     // (8, 32)
    gemm_kernel<false><<<g3, 256, GEMM_SMEM>>>(nullptr, out_w, out_b, out);
}

// round 4
// speedup vs baseline: 1.9249x; 1.6410x over previous
#include <cuda_runtime.h>
#include <cuda_fp16.h>
#include <math.h>
#include <stdint.h>

#define NNODE   512
#define NGRAPH  8
#define E_DIM   1024
#define NHEADS  16
#define HD      64
#define NB      (NGRAPH*NHEADS)     // 128 heads
#define NROWS   (NNODE*NGRAPH)      // 4096
#define SCALING 0.125f              // 64^-0.5

// Scratch (device globals: allocation-free rule)
__device__ __half g_Xh [NROWS*E_DIM];      // query, fp16
__device__ __half g_Wih[3*E_DIM*E_DIM];    // in_w, fp16
__device__ __half g_Woh[E_DIM*E_DIM];      // out_w, fp16
__device__ __half g_Qh [NB*NNODE*HD];      // scaled Q, fp16
__device__ __half g_Kh [NB*NNODE*HD];
__device__ __half g_Vh [NB*NNODE*HD];
__device__ __half g_AOh[NROWS*E_DIM];      // attention out, fp16

// ---------------------------------------------------------------------------
// Helpers
// ---------------------------------------------------------------------------
__device__ __forceinline__ unsigned smem_u32(const void* p){
    return (unsigned)__cvta_generic_to_shared(p);
}
__device__ __forceinline__ void cp16(unsigned dst, const void* src){
    asm volatile("cp.async.cg.shared.global [%0], [%1], 16;\n" :: "r"(dst), "l"(src));
}
__device__ __forceinline__ void cp_commit(){ asm volatile("cp.async.commit_group;\n" ::: "memory"); }
template<int N> __device__ __forceinline__ void cp_wait(){
    asm volatile("cp.async.wait_group %0;\n" :: "n"(N) : "memory");
}
__device__ __forceinline__ float fast_tanh(float x){
    float e = __expf(2.f*x);
    return 1.f - __fdividef(2.f, e + 1.f);
}
__device__ __forceinline__ void mma_f16(float c[4], const unsigned a[4], const unsigned b[2]){
    asm volatile(
        "mma.sync.aligned.m16n8k16.row.col.f32.f16.f16.f32 "
        "{%0,%1,%2,%3}, {%4,%5,%6,%7}, {%8,%9}, {%0,%1,%2,%3};"
        : "+f"(c[0]), "+f"(c[1]), "+f"(c[2]), "+f"(c[3])
        : "r"(a[0]), "r"(a[1]), "r"(a[2]), "r"(a[3]), "r"(b[0]), "r"(b[1]));
}
__device__ __forceinline__ void ldm_x4(unsigned* r, uint32_t a){
    asm volatile("ldmatrix.sync.aligned.m8n8.x4.shared.b16 {%0,%1,%2,%3}, [%4];"
        : "=r"(r[0]), "=r"(r[1]), "=r"(r[2]), "=r"(r[3]) : "r"(a));
}
__device__ __forceinline__ void ldm_x4_t(unsigned* r, uint32_t a){
    asm volatile("ldmatrix.sync.aligned.m8n8.x4.trans.shared.b16 {%0,%1,%2,%3}, [%4];"
        : "=r"(r[0]), "=r"(r[1]), "=r"(r[2]), "=r"(r[3]) : "r"(a));
}

// ---------------------------------------------------------------------------
// fp32 -> fp16 convert pre-pass (query, in_w, out_w). 2M float4 total.
// ---------------------------------------------------------------------------
#define NQ4 (NROWS*E_DIM/4)        // 1048576
#define NI4 (3*E_DIM*E_DIM/4)      // 786432
#define NO4 (E_DIM*E_DIM/4)        // 262144
#define CVT_GRID ((NQ4+NI4+NO4)/256)   // 8192

__global__ __launch_bounds__(256)
void cvt_kernel(const float4* __restrict__ q, const float4* __restrict__ iw,
                const float4* __restrict__ ow)
{
    int i = blockIdx.x*256 + threadIdx.x;
    float4 v; __half2* dst;
    if (i < NQ4)            { v = q[i];          dst = (__half2*)g_Xh  + 2*(size_t)i; }
    else if (i < NQ4+NI4)   { int j = i-NQ4;     v = iw[j]; dst = (__half2*)g_Wih + 2*(size_t)j; }
    else                    { int j = i-NQ4-NI4; v = ow[j]; dst = (__half2*)g_Woh + 2*(size_t)j; }
    dst[0] = __floats2half2_rn(v.x, v.y);
    dst[1] = __floats2half2_rn(v.z, v.w);
}

// ---------------------------------------------------------------------------
// fp16 GEMM (fp32 accum): C[M,N] = Ah[M,1024] * Wh[N,1024]^T (+bias)
// BM=128 BN=128 BK=32(halves), 256 thr, warps 2x4, warp tile 64x32.
// 3-stage cp.async pipeline; ldmatrix fragments; padded stride 40 halves.
// QKV=true: epilogue scatters fp16 Q(scaled)/K/V; else fp32 out + bias.
// ---------------------------------------------------------------------------
#define H_ST  40                    // halves per smem row (32 + 8 pad) = 80 B
#define HA_BYTES (128*H_ST*2)       // 10240
#define HSTAGE  (2*HA_BYTES)        // 20480 (A+B)
#define HGEMM_SMEM (3*HSTAGE)       // 61440

template<bool QKV>
__global__ __launch_bounds__(256, 2)
void hgemm_kernel(const __half* __restrict__ Ain, const __half* __restrict__ Wh,
                  const float* __restrict__ bias, float* __restrict__ Cout)
{
    extern __shared__ char smem[];
    const uint32_t sb = smem_u32(smem);
    const __half* Ah = QKV ? Ain : (const __half*)g_AOh;

    const int tid = threadIdx.x;
    const int wid = tid >> 5, lane = tid & 31;
    const int wm  = wid >> 2, wn = wid & 3;
    const int g   = lane >> 2, tg = lane & 3;
    const int bm0 = blockIdx.y * 128;
    const int bn0 = blockIdx.x * 128;

    float acc[4][4][4];
    #pragma unroll
    for (int i=0;i<4;i++)
        #pragma unroll
        for (int j=0;j<4;j++)
            #pragma unroll
            for (int k=0;k<4;k++) acc[i][j][k]=0.f;

    const __half* Ag0 = Ah + (size_t)bm0 * E_DIM;
    const __half* Bg0 = Wh + (size_t)bn0 * E_DIM;

    #define HLOAD(t) do { \
        uint32_t s_ = sb + ((t)%3)*HSTAGE; \
        const __half* Ag = Ag0 + (t)*32; \
        const __half* Bg = Bg0 + (t)*32; \
        _Pragma("unroll") \
        for (int j = 0; j < 2; j++) { \
            int ci = tid + 256*j; \
            int row = ci >> 2, cc = ci & 3; \
            cp16(s_ + row*80 + cc*16, Ag + (size_t)row*E_DIM + cc*8); \
            cp16(s_ + HA_BYTES + row*80 + cc*16, Bg + (size_t)row*E_DIM + cc*8); \
        } \
        cp_commit(); \
    } while (0)

    HLOAD(0); HLOAD(1);
    for (int t = 0; t < 32; t++) {
        if (t + 1 < 32) cp_wait<1>(); else cp_wait<0>();
        __syncthreads();
        if (t + 2 < 32) HLOAD(t+2);

        uint32_t as_ = sb + (t%3)*HSTAGE;
        uint32_t bs_ = as_ + HA_BYTES;
        const uint32_t aoff = ((lane>>4)<<3)*2;                 // k-half select
        #pragma unroll
        for (int ks = 0; ks < 32; ks += 16) {
            unsigned a[4][4], b[4][2];
            #pragma unroll
            for (int mt = 0; mt < 4; mt++)
                ldm_x4(a[mt], as_ + (wm*64 + mt*16 + (lane&15))*80 + ks*2 + aoff);
            #pragma unroll
            for (int ntp = 0; ntp < 2; ntp++) {
                unsigned r[4];
                ldm_x4(r, bs_ + (wn*32 + ntp*16 + ((lane>>4)<<3) + (lane&7))*80
                          + (ks + (((lane>>3)&1)<<3))*2);
                b[ntp*2][0]=r[0]; b[ntp*2][1]=r[1];
                b[ntp*2+1][0]=r[2]; b[ntp*2+1][1]=r[3];
            }
            #pragma unroll
            for (int mt = 0; mt < 4; mt++)
                #pragma unroll
                for (int nt = 0; nt < 4; nt++)
                    mma_f16(acc[mt][nt], a[mt], b[nt]);
        }
    }
    #undef HLOAD

    if (QKV) {
        #pragma unroll
        for (int mt = 0; mt < 4; mt++)
            #pragma unroll
            for (int nt = 0; nt < 4; nt++)
                #pragma unroll
                for (int ii = 0; ii < 2; ii++) {
                    int r = bm0 + wm*64 + mt*16 + g + ii*8;
                    int c = bn0 + wn*32 + nt*8 + 2*tg;
                    float2 bv = *(const float2*)(bias + c);
                    float v0 = acc[mt][nt][ii*2]   + bv.x;
                    float v1 = acc[mt][nt][ii*2+1] + bv.y;
                    int which = c >> 10;
                    int e = c & 1023, h = e >> 6, d = e & 63;
                    int n = r >> 3, gg = r & 7;
                    int idx = ((gg*NHEADS + h)*NNODE + n)*HD + d;
                    if (which == 0)
                        *(__half2*)&g_Qh[idx] = __floats2half2_rn(v0*SCALING, v1*SCALING);
                    else if (which == 1)
                        *(__half2*)&g_Kh[idx] = __floats2half2_rn(v0, v1);
                    else
                        *(__half2*)&g_Vh[idx] = __floats2half2_rn(v0, v1);
                }
    } else {
        #pragma unroll
        for (int mt = 0; mt < 4; mt++)
            #pragma unroll
            for (int nt = 0; nt < 4; nt++)
                #pragma unroll
                for (int ii = 0; ii < 2; ii++) {
                    int r = bm0 + wm*64 + mt*16 + g + ii*8;
                    int c = bn0 + wn*32 + nt*8 + 2*tg;
                    float2 bv = *(const float2*)(bias + c);
                    float2 val = make_float2(acc[mt][nt][ii*2]   + bv.x,
                                             acc[mt][nt][ii*2+1] + bv.y);
                    *(float2*)&Cout[(size_t)r*E_DIM + c] = val;
                }
    }
}

// ---------------------------------------------------------------------------
// Flash-style fused attention, fp16 tiles + ldmatrix, fp32 softmax.
// One CTA per (head, 64-row block); 8 chunks of 64 KV. 256 thr (wm2 x wn4).
// ---------------------------------------------------------------------------
#define AT_ST 72     // halves per row (64 + 8 pad) = 144 B
#define ATTN_SMEM (4*64*AT_ST*2 + (64+64+256)*4)   // 38400

__device__ __forceinline__ void at_load64(__half* dst, const __half* src, int tid)
{
    #pragma unroll
    for (int j = 0; j < 2; j++) {
        int ci = tid + 256*j;                 // 512 chunks of 16B
        int row = ci >> 3, cc = ci & 7;
        cp16(smem_u32(dst + row*AT_ST) + cc*16, src + (size_t)row*HD + cc*8);
    }
}

__global__ __launch_bounds__(256, 2)
void attn_kernel(const float* __restrict__ bias, const float* __restrict__ gaw)
{
    extern __shared__ __half ash[];
    __half* Qs = ash;
    __half* Ks = Qs + 64*AT_ST;
    __half* Vs = Ks + 64*AT_ST;
    __half* Ps = Vs + 64*AT_ST;
    float* Mrow = (float*)(Ps + 64*AT_ST);
    float* Lrow = Mrow + 64;
    float* Red  = Lrow + 64;                  // [64][4]

    const int b   = blockIdx.x;               // head = gg*16 + h
    const int rb  = blockIdx.y;               // 64-row block
    const int tid = threadIdx.x;
    const int wid = tid >> 5, lane = tid & 31;
    const int wm  = wid >> 2, wn = wid & 3;
    const int g   = lane >> 2, tg = lane & 3;

    const __half* Kg = g_Kh + (size_t)b*NNODE*HD;
    const __half* Vg = g_Vh + (size_t)b*NNODE*HD;

    {
        const __half* Qg = g_Qh + ((size_t)b*NNODE + rb*64)*HD;
        at_load64(Qs, Qg, tid);
        at_load64(Ks, Kg, tid);
        cp_commit();
    }
    if (tid < 64) { Mrow[tid] = -1e30f; Lrow[tid] = 0.f; }

    float o[2][2][4];
    #pragma unroll
    for (int i=0;i<2;i++)
        #pragma unroll
        for (int j=0;j<2;j++)
            #pragma unroll
            for (int k=0;k<4;k++) o[i][j][k]=0.f;

    const float* bp0 = bias + ((size_t)b*NNODE + rb*64)*NNODE;
    const float* gp0 = gaw  + ((size_t)b*NNODE + rb*64)*NNODE;

    const uint32_t qs_ = smem_u32(Qs), ks_ = smem_u32(Ks);
    const uint32_t vs_ = smem_u32(Vs), ps_ = smem_u32(Ps);

    for (int c = 0; c < 8; c++) {
        // prefetch bias/gaw for this chunk into registers
        float2 breg[8], greg[8];
        #pragma unroll
        for (int mt = 0; mt < 2; mt++)
            #pragma unroll
            for (int ii = 0; ii < 2; ii++)
                #pragma unroll
                for (int nt = 0; nt < 2; nt++) {
                    int lr = wm*32 + mt*16 + ii*8 + g;
                    int lc = c*64 + wn*16 + nt*8 + 2*tg;
                    int idx = (mt*2 + ii)*2 + nt;
                    breg[idx] = *(const float2*)(bp0 + (size_t)lr*NNODE + lc);
                    greg[idx] = *(const float2*)(gp0 + (size_t)lr*NNODE + lc);
                }

        __syncthreads();                 // all warps done with Vs (prev PV)
        at_load64(Vs, Vg + (size_t)c*64*HD, tid);
        cp_commit();
        cp_wait<1>();                    // K_c (and Q) ready
        __syncthreads();

        // ---- QK: s[2][2][4] over 64-wide chunk, k = hd = 64 ----
        float s[2][2][4];
        #pragma unroll
        for (int i=0;i<2;i++)
            #pragma unroll
            for (int j=0;j<2;j++)
                #pragma unroll
                for (int k=0;k<4;k++) s[i][j][k]=0.f;

        #pragma unroll
        for (int ks = 0; ks < HD; ks += 16) {
            unsigned a[2][4], bb[2][2];
            #pragma unroll
            for (int mt = 0; mt < 2; mt++)
                ldm_x4(a[mt], qs_ + (wm*32 + mt*16 + (lane&15))*144
                              + (ks + ((lane>>4)<<3))*2);
            {
                unsigned r[4];
                ldm_x4(r, ks_ + (wn*16 + ((lane>>4)<<3) + (lane&7))*144
                          + (ks + (((lane>>3)&1)<<3))*2);
                bb[0][0]=r[0]; bb[0][1]=r[1]; bb[1][0]=r[2]; bb[1][1]=r[3];
            }
            #pragma unroll
            for (int mt = 0; mt < 2; mt++)
                #pragma unroll
                for (int nt = 0; nt < 2; nt++)
                    mma_f16(s[mt][nt], a[mt], bb[nt]);
        }

        // + bias
        #pragma unroll
        for (int mt = 0; mt < 2; mt++)
            #pragma unroll
            for (int ii = 0; ii < 2; ii++)
                #pragma unroll
                for (int nt = 0; nt < 2; nt++) {
                    int idx = (mt*2 + ii)*2 + nt;
                    s[mt][nt][ii*2]   += breg[idx].x;
                    s[mt][nt][ii*2+1] += breg[idx].y;
                }

        // ---- chunk row max ----
        #pragma unroll
        for (int mt = 0; mt < 2; mt++)
            #pragma unroll
            for (int ii = 0; ii < 2; ii++) {
                float v = fmaxf(fmaxf(s[mt][0][ii*2], s[mt][0][ii*2+1]),
                                fmaxf(s[mt][1][ii*2], s[mt][1][ii*2+1]));
                v = fmaxf(v, __shfl_xor_sync(0xffffffffu, v, 1));
                v = fmaxf(v, __shfl_xor_sync(0xffffffffu, v, 2));
                if (tg == 0) Red[(wm*32 + mt*16 + ii*8 + g)*4 + wn] = v;
            }
        __syncthreads();

        float mnew[2][2], alpha[2][2], lold[2][2];
        #pragma unroll
        for (int mt = 0; mt < 2; mt++)
            #pragma unroll
            for (int ii = 0; ii < 2; ii++) {
                int row = wm*32 + mt*16 + ii*8 + g;
                float mc = fmaxf(fmaxf(Red[row*4], Red[row*4+1]),
                                 fmaxf(Red[row*4+2], Red[row*4+3]));
                float mo = Mrow[row];
                lold[mt][ii] = Lrow[row];
                float mn = fmaxf(mo, mc);
                mnew[mt][ii]  = mn;
                alpha[mt][ii] = __expf(mo - mn);
            }

        // ---- p = exp(s - mnew), row sums ----
        float psum[2][2];
        #pragma unroll
        for (int mt = 0; mt < 2; mt++)
            #pragma unroll
            for (int ii = 0; ii < 2; ii++) {
                float p0 = __expf(s[mt][0][ii*2]   - mnew[mt][ii]);
                float p1 = __expf(s[mt][0][ii*2+1] - mnew[mt][ii]);
                float p2 = __expf(s[mt][1][ii*2]   - mnew[mt][ii]);
                float p3 = __expf(s[mt][1][ii*2+1] - mnew[mt][ii]);
                s[mt][0][ii*2] = p0; s[mt][0][ii*2+1] = p1;
                s[mt][1][ii*2] = p2; s[mt][1][ii*2+1] = p3;
                float v = (p0 + p1) + (p2 + p3);
                v += __shfl_xor_sync(0xffffffffu, v, 1);
                v += __shfl_xor_sync(0xffffffffu, v, 2);
                psum[mt][ii] = v;
            }
        __syncthreads();   // Red reuse guard
        #pragma unroll
        for (int mt = 0; mt < 2; mt++)
            #pragma unroll
            for (int ii = 0; ii < 2; ii++)
                if (tg == 0) Red[(wm*32 + mt*16 + ii*8 + g)*4 + wn] = psum[mt][ii];
        __syncthreads();
        if (wn == 0 && tg == 0) {
            #pragma unroll
            for (int mt = 0; mt < 2; mt++)
                #pragma unroll
                for (int ii = 0; ii < 2; ii++) {
                    int row = wm*32 + mt*16 + ii*8 + g;
                    float sc = (Red[row*4] + Red[row*4+1]) + (Red[row*4+2] + Red[row*4+3]);
                    Lrow[row] = alpha[mt][ii]*lold[mt][ii] + sc;
                    Mrow[row] = mnew[mt][ii];
                }
        }

        // ---- P = p * tanh(gaw) -> fp16 smem; rescale o ----
        #pragma unroll
        for (int mt = 0; mt < 2; mt++)
            #pragma unroll
            for (int ii = 0; ii < 2; ii++)
                #pragma unroll
                for (int nt = 0; nt < 2; nt++) {
                    int idx = (mt*2 + ii)*2 + nt;
                    int lr = wm*32 + mt*16 + ii*8 + g;
                    int lc = wn*16 + nt*8 + 2*tg;
                    *(__half2*)&Ps[lr*AT_ST + lc] =
                        __floats2half2_rn(s[mt][nt][ii*2]   * fast_tanh(greg[idx].x),
                                          s[mt][nt][ii*2+1] * fast_tanh(greg[idx].y));
                }
        #pragma unroll
        for (int mt = 0; mt < 2; mt++)
            #pragma unroll
            for (int nt = 0; nt < 2; nt++)
                #pragma unroll
                for (int k = 0; k < 4; k++)
                    o[mt][nt][k] *= alpha[mt][k>>1];

        // prefetch K_{c+1} (Ks free: all warps past QK mma via syncs above)
        if (c < 7) at_load64(Ks, Kg + (size_t)(c+1)*64*HD, tid);
        cp_commit();
        cp_wait<1>();                    // V_c ready
        __syncthreads();                 // Ps visible

        // ---- PV: o += P[64x64] * V[64x64] ----
        #pragma unroll
        for (int ks = 0; ks < 64; ks += 16) {
            unsigned a[2][4], bb[2][2];
            #pragma unroll
            for (int mt = 0; mt < 2; mt++)
                ldm_x4(a[mt], ps_ + (wm*32 + mt*16 + (lane&15))*144
                              + (ks + ((lane>>4)<<3))*2);
            {
                unsigned r[4];
                ldm_x4_t(r, vs_ + (ks + (((lane>>3)&1)<<3) + (lane&7))*144
                            + (wn*16 + ((lane>>4)<<3))*2);
                bb[0][0]=r[0]; bb[0][1]=r[1]; bb[1][0]=r[2]; bb[1][1]=r[3];
            }
            #pragma unroll
            for (int mt = 0; mt < 2; mt++)
                #pragma unroll
                for (int nt = 0; nt < 2; nt++)
                    mma_f16(o[mt][nt], a[mt], bb[nt]);
        }
    }

    __syncthreads();
    // normalize, write fp16 to g_AOh[(n*8+gg)*1024 + h*64 + d]
    const int gg = b >> 4, h = b & 15;
    #pragma unroll
    for (int mt = 0; mt < 2; mt++)
        #pragma unroll
        for (int ii = 0; ii < 2; ii++) {
            int row = wm*32 + mt*16 + ii*8 + g;
            float inv = __fdividef(1.f, Lrow[row]);
            int n = rb*64 + row;
            #pragma unroll
            for (int nt = 0; nt < 2; nt++) {
                int d = wn*16 + nt*8 + 2*tg;
                *(__half2*)&g_AOh[(size_t)(n*NGRAPH + gg)*E_DIM + h*HD + d] =
                    __floats2half2_rn(o[mt][nt][ii*2] * inv, o[mt][nt][ii*2+1] * inv);
            }
        }
}

// ---------------------------------------------------------------------------
extern "C" void kernel_launch(void* const* d_in, const int* in_sizes, int n_in,
                              void* d_out, int out_size)
{
    const float* query    = (const float*)d_in[0];
    const float* attnbias = (const float*)d_in[1];
    const float* gaw      = (const float*)d_in[2];
    const float* in_w     = (const float*)d_in[3];
    const float* in_b     = (const float*)d_in[4];
    const float* out_w    = (const float*)d_in[5];
    const float* out_b    = (const float*)d_in[6];
    float* out = (float*)d_out;

    static int configured = 0;
    if (!configured) {
        cudaFuncSetAttribute(hgemm_kernel<true>,
                             cudaFuncAttributeMaxDynamicSharedMemorySize, HGEMM_SMEM);
        cudaFuncSetAttribute(hgemm_kernel<false>,
                             cudaFuncAttributeMaxDynamicSharedMemorySize, HGEMM_SMEM);
        cudaFuncSetAttribute(attn_kernel,
                             cudaFuncAttributeMaxDynamicSharedMemorySize, ATTN_SMEM);
        configured = 1;
    }

    cvt_kernel<<<CVT_GRID, 256>>>((const float4*)query, (const float4*)in_w,
                                  (const float4*)out_w);

    __half *xh, *wih, *woh;
    cudaGetSymbolAddress((void**)&xh,  g_Xh);
    cudaGetSymbolAddress((void**)&wih, g_Wih);
    cudaGetSymbolAddress((void**)&woh, g_Woh);

    dim3 g1(3*E_DIM/128, NROWS/128);     // (24, 32)
    hgemm_kernel<true><<<g1, 256, HGEMM_SMEM>>>(xh, wih, in_b, nullptr);

    dim3 g2(NB, NNODE/64);               // (128, 8)
    attn_kernel<<<g2, 256, ATTN_SMEM>>>(attnbias, gaw);

    dim3 g3(E_DIM/128, NROWS/128);       // (8, 32)
    hgemm_kernel<false><<<g3, 256, HGEMM_SMEM>>>(nullptr, woh, out_b, out);
}

// round 5
// speedup vs baseline: 2.1707x; 1.1277x over previous
#include <cuda_runtime.h>
#include <cuda_fp16.h>
#include <math.h>
#include <stdint.h>

#define NNODE   512
#define NGRAPH  8
#define E_DIM   1024
#define NHEADS  16
#define HD      64
#define NB      (NGRAPH*NHEADS)     // 128 heads
#define NROWS   (NNODE*NGRAPH)      // 4096
#define SCALING 0.125f              // 64^-0.5

// Scratch (device globals: allocation-free rule)
__device__ __half g_Xh [NROWS*E_DIM];      // query, fp16
__device__ __half g_Wih[3*E_DIM*E_DIM];    // in_w, fp16
__device__ __half g_Woh[E_DIM*E_DIM];      // out_w, fp16
__device__ __half g_Qh [NB*NNODE*HD];      // scaled Q, fp16
__device__ __half g_Kh [NB*NNODE*HD];
__device__ __half g_Vh [NB*NNODE*HD];
__device__ __half g_AOh[NROWS*E_DIM];      // attention out, fp16

// ---------------------------------------------------------------------------
// Helpers
// ---------------------------------------------------------------------------
__device__ __forceinline__ unsigned smem_u32(const void* p){
    return (unsigned)__cvta_generic_to_shared(p);
}
__device__ __forceinline__ void cp16(unsigned dst, const void* src){
    asm volatile("cp.async.cg.shared.global [%0], [%1], 16;\n" :: "r"(dst), "l"(src));
}
__device__ __forceinline__ void cp_commit(){ asm volatile("cp.async.commit_group;\n" ::: "memory"); }
template<int N> __device__ __forceinline__ void cp_wait(){
    asm volatile("cp.async.wait_group %0;\n" :: "n"(N) : "memory");
}
__device__ __forceinline__ float fast_tanh(float x){
    float e = __expf(2.f*x);
    return 1.f - __fdividef(2.f, e + 1.f);
}
__device__ __forceinline__ void mma_f16(float c[4], const unsigned a[4], const unsigned b[2]){
    asm volatile(
        "mma.sync.aligned.m16n8k16.row.col.f32.f16.f16.f32 "
        "{%0,%1,%2,%3}, {%4,%5,%6,%7}, {%8,%9}, {%0,%1,%2,%3};"
        : "+f"(c[0]), "+f"(c[1]), "+f"(c[2]), "+f"(c[3])
        : "r"(a[0]), "r"(a[1]), "r"(a[2]), "r"(a[3]), "r"(b[0]), "r"(b[1]));
}
__device__ __forceinline__ void ldm_x4(unsigned* r, uint32_t a){
    asm volatile("ldmatrix.sync.aligned.m8n8.x4.shared.b16 {%0,%1,%2,%3}, [%4];"
        : "=r"(r[0]), "=r"(r[1]), "=r"(r[2]), "=r"(r[3]) : "r"(a));
}
__device__ __forceinline__ void ldm_x4_t(unsigned* r, uint32_t a){
    asm volatile("ldmatrix.sync.aligned.m8n8.x4.trans.shared.b16 {%0,%1,%2,%3}, [%4];"
        : "=r"(r[0]), "=r"(r[1]), "=r"(r[2]), "=r"(r[3]) : "r"(a));
}
__device__ __forceinline__ unsigned pack_h2(float a, float b){
    __half2 h = __floats2half2_rn(a, b);
    return *(unsigned*)&h;
}

// ---------------------------------------------------------------------------
// fp32 -> fp16 convert pre-pass (query, in_w, out_w)
// ---------------------------------------------------------------------------
#define NQ4 (NROWS*E_DIM/4)        // 1048576
#define NI4 (3*E_DIM*E_DIM/4)      // 786432
#define NO4 (E_DIM*E_DIM/4)        // 262144
#define CVT_GRID ((NQ4+NI4+NO4)/256)

__global__ __launch_bounds__(256)
void cvt_kernel(const float4* __restrict__ q, const float4* __restrict__ iw,
                const float4* __restrict__ ow)
{
    int i = blockIdx.x*256 + threadIdx.x;
    float4 v; __half2* dst;
    if (i < NQ4)            { v = q[i];          dst = (__half2*)g_Xh  + 2*(size_t)i; }
    else if (i < NQ4+NI4)   { int j = i-NQ4;     v = iw[j]; dst = (__half2*)g_Wih + 2*(size_t)j; }
    else                    { int j = i-NQ4-NI4; v = ow[j]; dst = (__half2*)g_Woh + 2*(size_t)j; }
    dst[0] = __floats2half2_rn(v.x, v.y);
    dst[1] = __floats2half2_rn(v.z, v.w);
}

// ---------------------------------------------------------------------------
// fp16 GEMM (fp32 accum): C[M,N] = Ah[M,1024] * Wh[N,1024]^T (+bias)
// BM=128 BN=128 BK=32 halves. 128 thr = 4 warps (2x2), warp tile 64x64.
// 3-stage cp.async pipeline; ldmatrix fragments; stride 40 halves (80 B).
// ---------------------------------------------------------------------------
#define H_ST  40
#define HA_BYTES (128*H_ST*2)       // 10240
#define HSTAGE  (2*HA_BYTES)        // 20480
#define HGEMM_SMEM (3*HSTAGE)       // 61440

template<bool QKV>
__global__ __launch_bounds__(128, 2)
void hgemm_kernel(const __half* __restrict__ Ain, const __half* __restrict__ Wh,
                  const float* __restrict__ bias, float* __restrict__ Cout)
{
    extern __shared__ char smem[];
    const uint32_t sb = smem_u32(smem);
    const __half* Ah = QKV ? Ain : (const __half*)g_AOh;

    const int tid = threadIdx.x;
    const int wid = tid >> 5, lane = tid & 31;
    const int wm  = wid >> 1, wn = wid & 1;       // 2x2 warp grid
    const int g   = lane >> 2, tg = lane & 3;
    const int bm0 = blockIdx.y * 128;
    const int bn0 = blockIdx.x * 128;

    float acc[4][8][4];
    #pragma unroll
    for (int i=0;i<4;i++)
        #pragma unroll
        for (int j=0;j<8;j++)
            #pragma unroll
            for (int k=0;k<4;k++) acc[i][j][k]=0.f;

    const __half* Ag0 = Ah + (size_t)bm0 * E_DIM;
    const __half* Bg0 = Wh + (size_t)bn0 * E_DIM;

    #define HLOAD(t) do { \
        uint32_t s_ = sb + ((t)%3)*HSTAGE; \
        const __half* Ag = Ag0 + (t)*32; \
        const __half* Bg = Bg0 + (t)*32; \
        _Pragma("unroll") \
        for (int j = 0; j < 4; j++) { \
            int ci = tid + 128*j; \
            int row = ci >> 2, cc = ci & 3; \
            cp16(s_ + row*80 + cc*16, Ag + (size_t)row*E_DIM + cc*8); \
            cp16(s_ + HA_BYTES + row*80 + cc*16, Bg + (size_t)row*E_DIM + cc*8); \
        } \
        cp_commit(); \
    } while (0)

    HLOAD(0); HLOAD(1);
    for (int t = 0; t < 32; t++) {
        if (t + 1 < 32) cp_wait<1>(); else cp_wait<0>();
        __syncthreads();
        if (t + 2 < 32) HLOAD(t+2);

        uint32_t as_ = sb + (t%3)*HSTAGE;
        uint32_t bs_ = as_ + HA_BYTES;
        #pragma unroll
        for (int ks = 0; ks < 32; ks += 16) {
            unsigned a[4][4], b[8][2];
            #pragma unroll
            for (int mt = 0; mt < 4; mt++)
                ldm_x4(a[mt], as_ + (wm*64 + mt*16 + (lane&15))*80
                              + (ks + ((lane>>4)<<3))*2);
            #pragma unroll
            for (int np = 0; np < 4; np++) {
                unsigned r[4];
                ldm_x4(r, bs_ + (wn*64 + np*16 + ((lane>>4)<<3) + (lane&7))*80
                          + (ks + (((lane>>3)&1)<<3))*2);
                b[2*np][0]=r[0]; b[2*np][1]=r[1];
                b[2*np+1][0]=r[2]; b[2*np+1][1]=r[3];
            }
            #pragma unroll
            for (int mt = 0; mt < 4; mt++)
                #pragma unroll
                for (int nt = 0; nt < 8; nt++)
                    mma_f16(acc[mt][nt], a[mt], b[nt]);
        }
    }
    #undef HLOAD

    if (QKV) {
        #pragma unroll
        for (int mt = 0; mt < 4; mt++)
            #pragma unroll
            for (int nt = 0; nt < 8; nt++)
                #pragma unroll
                for (int ii = 0; ii < 2; ii++) {
                    int r = bm0 + wm*64 + mt*16 + g + ii*8;
                    int c = bn0 + wn*64 + nt*8 + 2*tg;
                    float2 bv = *(const float2*)(bias + c);
                    float v0 = acc[mt][nt][ii*2]   + bv.x;
                    float v1 = acc[mt][nt][ii*2+1] + bv.y;
                    int which = c >> 10;
                    int e = c & 1023, h = e >> 6, d = e & 63;
                    int n = r >> 3, gg = r & 7;
                    int idx = ((gg*NHEADS + h)*NNODE + n)*HD + d;
                    if (which == 0)
                        *(__half2*)&g_Qh[idx] = __floats2half2_rn(v0*SCALING, v1*SCALING);
                    else if (which == 1)
                        *(__half2*)&g_Kh[idx] = __floats2half2_rn(v0, v1);
                    else
                        *(__half2*)&g_Vh[idx] = __floats2half2_rn(v0, v1);
                }
    } else {
        #pragma unroll
        for (int mt = 0; mt < 4; mt++)
            #pragma unroll
            for (int nt = 0; nt < 8; nt++)
                #pragma unroll
                for (int ii = 0; ii < 2; ii++) {
                    int r = bm0 + wm*64 + mt*16 + g + ii*8;
                    int c = bn0 + wn*64 + nt*8 + 2*tg;
                    float2 bv = *(const float2*)(bias + c);
                    float2 val = make_float2(acc[mt][nt][ii*2]   + bv.x,
                                             acc[mt][nt][ii*2+1] + bv.y);
                    *(float2*)&Cout[(size_t)r*E_DIM + c] = val;
                }
    }
}

// ---------------------------------------------------------------------------
// Flash attention, warp-private softmax. 128 thr = 4 warps x 16 rows.
// P stays in registers (QK acc layout == PV A-frag layout). Q-frags cached.
// K/V double-buffered, ONE __syncthreads per chunk.
// ---------------------------------------------------------------------------
#define AT_ST 72     // halves per row (64 + 8 pad) = 144 B
#define ATTN_SMEM (5*64*AT_ST*2)    // Q + K0 K1 V0 V1 = 46080

__device__ __forceinline__ void at_load64(__half* dst, const __half* src, int tid)
{
    #pragma unroll
    for (int j = 0; j < 4; j++) {
        int ci = tid + 128*j;                 // 512 chunks of 16B
        int row = ci >> 3, cc = ci & 7;
        cp16(smem_u32(dst + row*AT_ST) + cc*16, src + (size_t)row*HD + cc*8);
    }
}

__global__ __launch_bounds__(128, 2)
void attn_kernel(const float* __restrict__ bias, const float* __restrict__ gaw)
{
    extern __shared__ __half ash[];
    __half* Qs = ash;
    __half* K0 = ash + 1*64*AT_ST;
    __half* K1 = ash + 2*64*AT_ST;
    __half* V0 = ash + 3*64*AT_ST;
    __half* V1 = ash + 4*64*AT_ST;

    const int b   = blockIdx.x;               // head = gg*16 + h
    const int rb  = blockIdx.y;               // 64-row block
    const int tid = threadIdx.x;
    const int wid = tid >> 5, lane = tid & 31;
    const int g   = lane >> 2, tg = lane & 3;

    const __half* Kg = g_Kh + (size_t)b*NNODE*HD;
    const __half* Vg = g_Vh + (size_t)b*NNODE*HD;

    // preload Q + K0 + V0 as one group
    at_load64(Qs, g_Qh + ((size_t)b*NNODE + rb*64)*HD, tid);
    at_load64(K0, Kg, tid);
    at_load64(V0, Vg, tid);
    cp_commit();

    float m0 = -1e30f, m1 = -1e30f, l0 = 0.f, l1 = 0.f;
    float o[8][4];
    #pragma unroll
    for (int j=0;j<8;j++)
        #pragma unroll
        for (int k=0;k<4;k++) o[j][k]=0.f;
    unsigned qf[4][4];

    const float* bp = bias + ((size_t)b*NNODE + rb*64 + wid*16 + g)*NNODE + 2*tg;
    const float* gp = gaw  + ((size_t)b*NNODE + rb*64 + wid*16 + g)*NNODE + 2*tg;
    const uint32_t qs_ = smem_u32(Qs);
    const uint32_t kb_[2] = { smem_u32(K0), smem_u32(K1) };
    const uint32_t vb_[2] = { smem_u32(V0), smem_u32(V1) };

    for (int c = 0; c < 8; c++) {
        cp_wait<0>();
        __syncthreads();                   // data visible; prev buffers free

        if (c == 0) {
            #pragma unroll
            for (int t = 0; t < 4; t++)
                ldm_x4(qf[t], qs_ + (wid*16 + (lane&15))*144
                              + (t*16 + ((lane>>4)<<3))*2);
        }
        if (c + 1 < 8) {
            at_load64(c & 1 ? K0 : K1, Kg + (size_t)(c+1)*64*HD, tid);
            at_load64(c & 1 ? V0 : V1, Vg + (size_t)(c+1)*64*HD, tid);
            cp_commit();
        }

        // prefetch bias/gaw for this chunk into registers
        float2 breg[8][2], greg[8][2];
        #pragma unroll
        for (int j = 0; j < 8; j++)
            #pragma unroll
            for (int h = 0; h < 2; h++) {
                breg[j][h] = *(const float2*)(bp + (size_t)h*8*NNODE + c*64 + j*8);
                greg[j][h] = *(const float2*)(gp + (size_t)h*8*NNODE + c*64 + j*8);
            }

        // ---- QK: s[8 n8-tiles][4], K from smem, Q frags cached ----
        float s[8][4];
        #pragma unroll
        for (int j=0;j<8;j++)
            #pragma unroll
            for (int k=0;k<4;k++) s[j][k]=0.f;

        const uint32_t kbase = kb_[c & 1];
        #pragma unroll
        for (int t = 0; t < 4; t++) {
            #pragma unroll
            for (int np = 0; np < 4; np++) {
                unsigned r[4];
                ldm_x4(r, kbase + (np*16 + ((lane>>4)<<3) + (lane&7))*144
                          + (t*16 + (((lane>>3)&1)<<3))*2);
                unsigned b0[2] = {r[0], r[1]}, b1[2] = {r[2], r[3]};
                mma_f16(s[2*np],   qf[t], b0);
                mma_f16(s[2*np+1], qf[t], b1);
            }
        }

        // + bias
        #pragma unroll
        for (int j = 0; j < 8; j++) {
            s[j][0] += breg[j][0].x;  s[j][1] += breg[j][0].y;
            s[j][2] += breg[j][1].x;  s[j][3] += breg[j][1].y;
        }

        // ---- warp-local softmax (rows g and g+8 of this warp's 16) ----
        float mx0 = -1e30f, mx1 = -1e30f;
        #pragma unroll
        for (int j = 0; j < 8; j++) {
            mx0 = fmaxf(mx0, fmaxf(s[j][0], s[j][1]));
            mx1 = fmaxf(mx1, fmaxf(s[j][2], s[j][3]));
        }
        mx0 = fmaxf(mx0, __shfl_xor_sync(0xffffffffu, mx0, 1));
        mx0 = fmaxf(mx0, __shfl_xor_sync(0xffffffffu, mx0, 2));
        mx1 = fmaxf(mx1, __shfl_xor_sync(0xffffffffu, mx1, 1));
        mx1 = fmaxf(mx1, __shfl_xor_sync(0xffffffffu, mx1, 2));

        float mn0 = fmaxf(m0, mx0), mn1 = fmaxf(m1, mx1);
        float al0 = __expf(m0 - mn0), al1 = __expf(m1 - mn1);
        m0 = mn0; m1 = mn1;

        float sum0 = 0.f, sum1 = 0.f;
        #pragma unroll
        for (int j = 0; j < 8; j++) {
            s[j][0] = __expf(s[j][0] - mn0);
            s[j][1] = __expf(s[j][1] - mn0);
            s[j][2] = __expf(s[j][2] - mn1);
            s[j][3] = __expf(s[j][3] - mn1);
            sum0 += s[j][0] + s[j][1];
            sum1 += s[j][2] + s[j][3];
        }
        sum0 += __shfl_xor_sync(0xffffffffu, sum0, 1);
        sum0 += __shfl_xor_sync(0xffffffffu, sum0, 2);
        sum1 += __shfl_xor_sync(0xffffffffu, sum1, 1);
        sum1 += __shfl_xor_sync(0xffffffffu, sum1, 2);
        l0 = al0*l0 + sum0;
        l1 = al1*l1 + sum1;

        // ---- P = p * tanh(gaw) (registers), rescale o ----
        #pragma unroll
        for (int j = 0; j < 8; j++) {
            s[j][0] *= fast_tanh(greg[j][0].x);
            s[j][1] *= fast_tanh(greg[j][0].y);
            s[j][2] *= fast_tanh(greg[j][1].x);
            s[j][3] *= fast_tanh(greg[j][1].y);
            o[j][0] *= al0; o[j][1] *= al0;
            o[j][2] *= al1; o[j][3] *= al1;
        }

        // pack P into PV A-fragments (no smem round-trip)
        unsigned pa[4][4];
        #pragma unroll
        for (int t = 0; t < 4; t++) {
            pa[t][0] = pack_h2(s[2*t][0],   s[2*t][1]);
            pa[t][1] = pack_h2(s[2*t][2],   s[2*t][3]);
            pa[t][2] = pack_h2(s[2*t+1][0], s[2*t+1][1]);
            pa[t][3] = pack_h2(s[2*t+1][2], s[2*t+1][3]);
        }

        // ---- PV: o[16x64] += P[16x64] * V[64x64] (V via trans ldmatrix) ----
        const uint32_t vbase = vb_[c & 1];
        #pragma unroll
        for (int t = 0; t < 4; t++) {
            #pragma unroll
            for (int jp = 0; jp < 4; jp++) {
                unsigned r[4];
                ldm_x4_t(r, vbase + (t*16 + (((lane>>3)&1)<<3) + (lane&7))*144
                            + (jp*16 + ((lane>>4)<<3))*2);
                unsigned b0[2] = {r[0], r[1]}, b1[2] = {r[2], r[3]};
                mma_f16(o[2*jp],   pa[t], b0);
                mma_f16(o[2*jp+1], pa[t], b1);
            }
        }
    }

    // ---- epilogue: normalize, write fp16 to g_AOh ----
    const int gg = b >> 4, h = b & 15;
    const float inv0 = __fdividef(1.f, l0);
    const float inv1 = __fdividef(1.f, l1);
    const int n0 = rb*64 + wid*16 + g;
    #pragma unroll
    for (int j = 0; j < 8; j++) {
        int d = j*8 + 2*tg;
        *(__half2*)&g_AOh[(size_t)(n0*NGRAPH + gg)*E_DIM + h*HD + d] =
            __floats2half2_rn(o[j][0]*inv0, o[j][1]*inv0);
        *(__half2*)&g_AOh[(size_t)((n0+8)*NGRAPH + gg)*E_DIM + h*HD + d] =
            __floats2half2_rn(o[j][2]*inv1, o[j][3]*inv1);
    }
}

// ---------------------------------------------------------------------------
extern "C" void kernel_launch(void* const* d_in, const int* in_sizes, int n_in,
                              void* d_out, int out_size)
{
    const float* query    = (const float*)d_in[0];
    const float* attnbias = (const float*)d_in[1];
    const float* gaw      = (const float*)d_in[2];
    const float* in_w     = (const float*)d_in[3];
    const float* in_b     = (const float*)d_in[4];
    const float* out_w    = (const float*)d_in[5];
    const float* out_b    = (const float*)d_in[6];
    float* out = (float*)d_out;

    static int configured = 0;
    if (!configured) {
        cudaFuncSetAttribute(hgemm_kernel<true>,
                             cudaFuncAttributeMaxDynamicSharedMemorySize, HGEMM_SMEM);
        cudaFuncSetAttribute(hgemm_kernel<false>,
                             cudaFuncAttributeMaxDynamicSharedMemorySize, HGEMM_SMEM);
        cudaFuncSetAttribute(attn_kernel,
                             cudaFuncAttributeMaxDynamicSharedMemorySize, ATTN_SMEM);
        configured = 1;
    }

    cvt_kernel<<<CVT_GRID, 256>>>((const float4*)query, (const float4*)in_w,
                                  (const float4*)out_w);

    __half *xh, *wih, *woh;
    cudaGetSymbolAddress((void**)&xh,  g_Xh);
    cudaGetSymbolAddress((void**)&wih, g_Wih);
    cudaGetSymbolAddress((void**)&woh, g_Woh);

    dim3 g1(3*E_DIM/128, NROWS/128);     // (24, 32)
    hgemm_kernel<true><<<g1, 128, HGEMM_SMEM>>>(xh, wih, in_b, nullptr);

    dim3 g2(NB, NNODE/64);               // (128, 8)
    attn_kernel<<<g2, 128, ATTN_SMEM>>>(attnbias, gaw);

    dim3 g3(E_DIM/128, NROWS/128);       // (8, 32)
    hgemm_kernel<false><<<g3, 128, HGEMM_SMEM>>>(nullptr, woh, out_b, out);
}